// round 1
// baseline (speedup 1.0000x reference)
#include <cuda_runtime.h>
#include <cuda_bf16.h>

#define B_IMGS 64
#define CH 3
#define H_MAX 512
#define W_STRIDE 513            // stored width is W_max+1
#define OUT_H 224
#define OUT_W 224

__global__ __launch_bounds__(OUT_W) void center_crop_kernel(
    const float* __restrict__ x, float* __restrict__ out)
{
    const int bx = blockIdx.x;          // 0 .. B*OUT_H-1
    const int b  = bx / OUT_H;
    const int oy = bx - b * OUT_H;
    const int ox = threadIdx.x;         // 0 .. 223

    const float* img = x + (size_t)b * CH * H_MAX * W_STRIDE;

    // h at x[b,0,0,W_max], w at x[b,1,0,W_max]
    const float h = __ldg(img + (H_MAX - H_MAX) * 0 + (W_STRIDE - 1));
    const float w = __ldg(img + (size_t)H_MAX * W_STRIDE + (W_STRIDE - 1));

    const float min_dim = fminf(h, w);
    const float scale   = __fdiv_rn(256.0f, min_dim);   // IEEE rn, matches XLA
    const float h_res   = rintf(h * scale);             // round half-to-even = jnp.round
    const float w_res   = rintf(w * scale);
    const float top     = rintf((h_res - (float)OUT_H) * 0.5f);
    const float left    = rintf((w_res - (float)OUT_W) * 0.5f);

    // src_y = clip(((oy+top)+0.5)*h/h_res - 0.5, 0, h-1)   (same op order as ref)
    const float ys = ((float)oy + top) + 0.5f;
    const float xs = ((float)ox + left) + 0.5f;
    float sy = __fdiv_rn(ys * h, h_res) - 0.5f;
    float sx = __fdiv_rn(xs * w, w_res) - 0.5f;
    sy = fminf(fmaxf(sy, 0.0f), h - 1.0f);
    sx = fminf(fmaxf(sx, 0.0f), w - 1.0f);

    const float y0f = floorf(sy);
    const float x0f = floorf(sx);
    const float wy = sy - y0f;
    const float wxf = sx - x0f;

    const int hi = (int)h - 1;
    const int wi = (int)w - 1;
    int y0 = (int)y0f; y0 = min(max(y0, 0), hi);
    int x0 = (int)x0f; x0 = min(max(x0, 0), wi);
    const int y1 = min(y0 + 1, hi);
    const int x1 = min(x0 + 1, wi);

    const float w00 = (1.0f - wy) * (1.0f - wxf);
    const float w01 = (1.0f - wy) * wxf;
    const float w10 = wy * (1.0f - wxf);
    const float w11 = wy * wxf;

    const size_t r0 = (size_t)y0 * W_STRIDE;
    const size_t r1 = (size_t)y1 * W_STRIDE;

    float* o = out + (((size_t)b * CH) * OUT_H + oy) * OUT_W + ox;

#pragma unroll
    for (int c = 0; c < CH; c++) {
        const float* p = img + (size_t)c * H_MAX * W_STRIDE;
        const float v00 = __ldg(p + r0 + x0);
        const float v01 = __ldg(p + r0 + x1);
        const float v10 = __ldg(p + r1 + x0);
        const float v11 = __ldg(p + r1 + x1);
        o[(size_t)c * OUT_H * OUT_W] =
            v00 * w00 + v01 * w01 + v10 * w10 + v11 * w11;
    }
}

extern "C" void kernel_launch(void* const* d_in, const int* in_sizes, int n_in,
                              void* d_out, int out_size)
{
    const float* x = (const float*)d_in[0];
    float* out = (float*)d_out;
    dim3 grid(B_IMGS * OUT_H);
    dim3 block(OUT_W);
    center_crop_kernel<<<grid, block>>>(x, out);
}